// round 10
// baseline (speedup 1.0000x reference)
#include <cuda_runtime.h>
#include <math.h>

#define NT   512
#define TILE 64
#define HID  128
#define RS   132   // lane-stride 132 floats -> 4-bank quads tile all 32 banks

// per-CTA shared-memory float offsets (72 KB total -> 2 CTAs/SM)
#define OFF_H1   0        // 8448   h1row[s][j] stride RS
#define OFF_G2   8448     // 8448   g2row[s][k] stride RS  -> ends 16896
#define OFF_W1T  16896    // 512    W1T[j][i]
#define OFF_B1   17408    // 128
#define OFF_B2   17536    // 128
#define OFF_W3   17664    // 128
#define OFF_FT   17792    // 256    feat[s][4]
#define OFF_XD   18048    // 128    qd[s][2]
#define OFF_GF   18176    // 256    reduced gfeat [s][4]
#define OFF_PF   OFF_G2   // 4096   gfeat partials [jg][s][4] overlay G2 (dead)
#define SMEM_FLOATS 18432 // 73728 bytes

typedef unsigned long long ull;
union F4U2 { float4 f4; ull u[2]; };

__device__ __forceinline__ void ffma2(ull& acc, ull a, ull b) {
    asm("fma.rn.f32x2 %0, %1, %2, %0;" : "+l"(acc) : "l"(a), "l"(b));
}
__device__ __forceinline__ ull pack2(float lo, float hi) {
    ull r; asm("mov.b64 %0, {%1, %2};" : "=l"(r) : "f"(lo), "f"(hi)); return r;
}
__device__ __forceinline__ void unpack2(ull v, float& lo, float& hi) {
    asm("mov.b64 {%0, %1}, %2;" : "=f"(lo), "=f"(hi) : "l"(v));
}

__device__ __forceinline__ float tanh_fast(float x) {
    float a = fabsf(x);
    a = fminf(a, 20.0f);
    float e = __expf(-2.0f * a);
    float r = __fdividef(1.0f - e, 1.0f + e);
    return copysignf(r, x);
}

__global__ __launch_bounds__(NT, 2)
void lnn_kernel(const float* __restrict__ X,
                const float* __restrict__ W1, const float* __restrict__ b1,
                const float* __restrict__ W2, const float* __restrict__ b2,
                const float* __restrict__ W3,
                float* __restrict__ out, int B)
{
    extern __shared__ float sm[];
    const int tid  = threadIdx.x;
    const int base = blockIdx.x * TILE;
    const int lane = tid & 31;
    const float4* __restrict__ W2v = (const float4*)W2;   // weights via L1 LDG

    // ---------------- Phase 0: stage small stuff only ---------------------
    if (tid < TILE) {
        int gs = base + tid;
        float4 x = make_float4(0.f, 0.f, 0.f, 0.f);
        if (gs < B) x = *(const float4*)&X[gs * 4];
        float s1, c1, s2, c2;
        sincosf(x.x, &s1, &c1);
        sincosf(x.y, &s2, &c2);
        sm[OFF_FT + tid * 4 + 0] = s1;
        sm[OFF_FT + tid * 4 + 1] = c1;
        sm[OFF_FT + tid * 4 + 2] = s2;
        sm[OFF_FT + tid * 4 + 3] = c2;
        sm[OFF_XD + tid * 2 + 0] = x.z;
        sm[OFF_XD + tid * 2 + 1] = x.w;
    } else {
        int t = tid - TILE;                       // 0..447
        for (int i = t; i < 4 * HID; i += NT - TILE) {
            int r = i >> 7, j = i & 127;          // W1 is [4][128]
            sm[OFF_W1T + j * 4 + r] = W1[i];
        }
        for (int i = t; i < HID; i += NT - TILE) {
            sm[OFF_B1 + i] = b1[i];
            sm[OFF_B2 + i] = b2[i];
            sm[OFF_W3 + i] = W3[i];
        }
    }
    __syncthreads();

    const int og8 = (tid >> 5) * 8;    // warp-uniform output group (k0 / j0)
    const int sA  = lane;              // samples lane, lane+32

    // ---------------- Phase A: h1row[s][j] = tanh(b1 + feat.W1T) ----------
    {
        const int s  = tid & 63;
        const int j0 = (tid >> 6) * 16;
        float4 f = *(const float4*)&sm[OFF_FT + s * 4];
        #pragma unroll
        for (int c = 0; c < 16; c += 4) {
            float hv[4];
            #pragma unroll
            for (int q = 0; q < 4; q++) {
                int j = j0 + c + q;
                float4 w = *(const float4*)&sm[OFF_W1T + j * 4];
                float z = sm[OFF_B1 + j] + f.x*w.x + f.y*w.y + f.z*w.z + f.w*w.w;
                hv[q] = tanh_fast(z);
            }
            *(float4*)&sm[OFF_H1 + s * RS + j0 + c]
                = make_float4(hv[0], hv[1], hv[2], hv[3]);
        }
    }
    __syncthreads();

    // ---------------- Phase B: z2 = h1@W2 (+b2); g2 = W3*sech^2 -----------
    // tile: 2 samples (lane, lane+32) x 8 k; weights via uniform LDG (L1)
    {
        const int k0 = og8;
        const int kq = k0 >> 2;
        ull acc[2][4];
        #pragma unroll
        for (int m = 0; m < 4; m++) {
            ull bp = pack2(sm[OFF_B2 + k0 + 2*m], sm[OFF_B2 + k0 + 2*m + 1]);
            acc[0][m] = bp; acc[1][m] = bp;
        }
        #pragma unroll 2
        for (int j = 0; j < HID; j += 4) {
            float4 hA = *(const float4*)&sm[OFF_H1 + sA * RS + j];
            float4 hB = *(const float4*)&sm[OFF_H1 + (sA + 32) * RS + j];
            float ha[4] = {hA.x, hA.y, hA.z, hA.w};
            float hb[4] = {hB.x, hB.y, hB.z, hB.w};
            #pragma unroll
            for (int q = 0; q < 4; q++) {
                F4U2 wlo, whi;
                wlo.f4 = __ldg(&W2v[(j + q) * 32 + kq]);
                whi.f4 = __ldg(&W2v[(j + q) * 32 + kq + 1]);
                ull hpA = pack2(ha[q], ha[q]);
                ull hpB = pack2(hb[q], hb[q]);
                ffma2(acc[0][0], hpA, wlo.u[0]); ffma2(acc[0][1], hpA, wlo.u[1]);
                ffma2(acc[0][2], hpA, whi.u[0]); ffma2(acc[0][3], hpA, whi.u[1]);
                ffma2(acc[1][0], hpB, wlo.u[0]); ffma2(acc[1][1], hpB, wlo.u[1]);
                ffma2(acc[1][2], hpB, whi.u[0]); ffma2(acc[1][3], hpB, whi.u[1]);
            }
        }
        #pragma unroll
        for (int u = 0; u < 2; u++) {
            int s = sA + 32 * u;
            float g[8];
            #pragma unroll
            for (int m = 0; m < 4; m++) {
                float z0, z1;
                unpack2(acc[u][m], z0, z1);
                float t0 = tanh_fast(z0), t1 = tanh_fast(z1);
                g[2*m]     = sm[OFF_W3 + k0 + 2*m]     * (1.0f - t0 * t0);
                g[2*m + 1] = sm[OFF_W3 + k0 + 2*m + 1] * (1.0f - t1 * t1);
            }
            *(float4*)&sm[OFF_G2 + s * RS + k0]     = make_float4(g[0], g[1], g[2], g[3]);
            *(float4*)&sm[OFF_G2 + s * RS + k0 + 4] = make_float4(g[4], g[5], g[6], g[7]);
        }
    }
    __syncthreads();

    // ---------------- Phase C: a = g2@W2^T (k-dot); g1; gfeat partials ----
    float pf[2][4];
    {
        const int j0 = og8;
        ull acc[2][8];
        #pragma unroll
        for (int u = 0; u < 2; u++)
            #pragma unroll
            for (int jj = 0; jj < 8; jj++) acc[u][jj] = 0ull;

        for (int k = 0; k < HID; k += 4) {
            F4U2 gA, gB;
            gA.f4 = *(const float4*)&sm[OFF_G2 + sA * RS + k];
            gB.f4 = *(const float4*)&sm[OFF_G2 + (sA + 32) * RS + k];
            #pragma unroll
            for (int jj = 0; jj < 8; jj++) {
                F4U2 w; w.f4 = __ldg(&W2v[(j0 + jj) * 32 + (k >> 2)]);
                ffma2(acc[0][jj], gA.u[0], w.u[0]);
                ffma2(acc[0][jj], gA.u[1], w.u[1]);
                ffma2(acc[1][jj], gB.u[0], w.u[0]);
                ffma2(acc[1][jj], gB.u[1], w.u[1]);
            }
        }
        // epilogue (registers only): g1 = a*(1-h^2), gfeat partials
        #pragma unroll
        for (int u = 0; u < 2; u++) {
            int s = sA + 32 * u;
            float4 h0  = *(const float4*)&sm[OFF_H1 + s * RS + j0];
            float4 h1v = *(const float4*)&sm[OFF_H1 + s * RS + j0 + 4];
            float hh[8] = {h0.x, h0.y, h0.z, h0.w, h1v.x, h1v.y, h1v.z, h1v.w};
            float gf0 = 0.f, gf1 = 0.f, gf2 = 0.f, gf3 = 0.f;
            #pragma unroll
            for (int jj = 0; jj < 8; jj++) {
                float lo, hi;
                unpack2(acc[u][jj], lo, hi);
                float a = lo + hi;
                float g1v = a * (1.0f - hh[jj] * hh[jj]);
                float4 w = *(const float4*)&sm[OFF_W1T + (j0 + jj) * 4];
                gf0 = fmaf(g1v, w.x, gf0);
                gf1 = fmaf(g1v, w.y, gf1);
                gf2 = fmaf(g1v, w.z, gf2);
                gf3 = fmaf(g1v, w.w, gf3);
            }
            pf[u][0] = gf0; pf[u][1] = gf1; pf[u][2] = gf2; pf[u][3] = gf3;
        }
    }
    __syncthreads();   // all G2 reads done -> PF may overlay G2

    {
        const int jg = tid >> 5;   // 16 j-groups
        *(float4*)&sm[OFF_PF + (jg * 64 + sA) * 4]
            = make_float4(pf[0][0], pf[0][1], pf[0][2], pf[0][3]);
        *(float4*)&sm[OFF_PF + (jg * 64 + sA + 32) * 4]
            = make_float4(pf[1][0], pf[1][1], pf[1][2], pf[1][3]);
    }
    __syncthreads();

    // ---------------- Reduce gfeat partials over the 16 j-groups ----------
    if (tid < 256) {
        int rs = tid >> 2, c = tid & 3;          // 64 s x 4 comps
        float a = 0.f;
        #pragma unroll
        for (int jg = 0; jg < 16; jg++)
            a += sm[OFF_PF + (jg * 64 + rs) * 4 + c];
        sm[OFF_GF + rs * 4 + c] = a;
    }
    __syncthreads();

    // ---------------- Final: analytic dynamics + output -------------------
    if (tid < TILE) {
        float4 gf = *(const float4*)&sm[OFF_GF + tid * 4];

        float w1 = sm[OFF_XD + tid * 2 + 0];
        float w2 = sm[OFF_XD + tid * 2 + 1];
        float s1 = sm[OFF_FT + tid * 4 + 0];
        float c1 = sm[OFF_FT + tid * 4 + 1];
        float s2 = sm[OFF_FT + tid * 4 + 2];
        float c2 = sm[OFF_FT + tid * 4 + 3];

        float sd = s1 * c2 - c1 * s2;      // sin(t1 - t2)
        float cd = c1 * c2 + s1 * s2;      // cos(t1 - t2)

        float dV1 = gf.x * c1 - gf.y * s1;
        float dV2 = gf.z * c2 - gf.w * s2;

        float tt  = w1 * w2 * sd;
        float dL1 = -tt - dV1;
        float dL2 =  tt - dV2;

        float cc = sd * (w2 - w1);
        float r1 = dL1 - w2 * cc;
        float r2 = dL2 - w1 * cc;

        float det  = 2.0f - cd * cd;
        float rdet = __fdividef(1.0f, det);
        float qdd1 = (r1 - cd * r2) * rdet;
        float qdd2 = (2.0f * r2 - cd * r1) * rdet;

        int gs = base + tid;
        if (gs < B)
            *(float4*)&out[gs * 4] = make_float4(w1, w2, qdd1, qdd2);
    }
}

extern "C" void kernel_launch(void* const* d_in, const int* in_sizes, int n_in,
                              void* d_out, int out_size)
{
    const float* X  = (const float*)d_in[0];
    const float* W1 = (const float*)d_in[1];
    const float* b1 = (const float*)d_in[2];
    const float* W2 = (const float*)d_in[3];
    const float* b2 = (const float*)d_in[4];
    const float* W3 = (const float*)d_in[5];
    // d_in[6] = b3: no effect on grad(V) -> unused
    float* out = (float*)d_out;

    int B = in_sizes[0] / 4;
    size_t smem = SMEM_FLOATS * sizeof(float);
    cudaFuncSetAttribute(lnn_kernel, cudaFuncAttributeMaxDynamicSharedMemorySize,
                         (int)smem);
    int grid = (B + TILE - 1) / TILE;
    lnn_kernel<<<grid, NT, smem>>>(X, W1, b1, W2, b2, W3, out, B);
}

// round 11
// speedup vs baseline: 1.5401x; 1.5401x over previous
#include <cuda_runtime.h>
#include <math.h>

#define NT   512
#define TILE 128
#define HID  128
#define RS   132   // lane-stride 132 floats -> 4-bank quads tile all 32 banks

// shared-memory float offsets (R8 layout)
#define OFF_W2   0        // 16384  W2[j][k] row-major
#define OFF_H1   16384    // 16896  h1row[s][j] stride RS    -> ends 33280
#define OFF_G2   33280    // 16896  g2row[s][k] stride RS    -> ends 50176
#define OFF_W1T  50176    // 512    W1T[j][i]
#define OFF_B1   50688    // 128
#define OFF_B2   50816    // 128
#define OFF_W3   50944    // 128
#define OFF_FT   51072    // 512    feat[s][4]
#define OFF_XD   51584    // 256    qd[s][2]
#define OFF_GF   51840    // 512    reduced gfeat [s][4]
#define OFF_PF   OFF_G2   // 8192   gfeat partials [jg][s][4] overlay G2 (dead)
#define SMEM_FLOATS 52352 // 209408 bytes

typedef unsigned long long ull;
union F4U2 { float4 f4; ull u[2]; };

__device__ __forceinline__ void ffma2(ull& acc, ull a, ull b) {
    asm("fma.rn.f32x2 %0, %1, %2, %0;" : "+l"(acc) : "l"(a), "l"(b));
}
__device__ __forceinline__ ull pack2(float lo, float hi) {
    ull r; asm("mov.b64 %0, {%1, %2};" : "=l"(r) : "f"(lo), "f"(hi)); return r;
}
__device__ __forceinline__ void unpack2(ull v, float& lo, float& hi) {
    asm("mov.b64 {%0, %1}, %2;" : "=f"(lo), "=f"(hi) : "l"(v));
}

// HW tanh: 1 MUFU op, ~5.8e-4 abs accuracy (vs 2 MUFU + 6 ALU for exp-based)
__device__ __forceinline__ float tanh_hw(float x) {
    float r;
    asm("tanh.approx.f32 %0, %1;" : "=f"(r) : "f"(x));
    return r;
}

__global__ __launch_bounds__(NT, 1)
void lnn_kernel(const float* __restrict__ X,
                const float* __restrict__ W1, const float* __restrict__ b1,
                const float* __restrict__ W2, const float* __restrict__ b2,
                const float* __restrict__ W3,
                float* __restrict__ out, int B)
{
    extern __shared__ float sm[];
    const int tid  = threadIdx.x;
    const int base = blockIdx.x * TILE;
    const int lane = tid & 31;

    // ---------------- Phase 0: stage (split threads) ----------------------
    if (tid < TILE) {
        int gs = base + tid;
        float4 x = make_float4(0.f, 0.f, 0.f, 0.f);
        if (gs < B) x = *(const float4*)&X[gs * 4];
        float s1, c1, s2, c2;
        sincosf(x.x, &s1, &c1);
        sincosf(x.y, &s2, &c2);
        sm[OFF_FT + tid * 4 + 0] = s1;
        sm[OFF_FT + tid * 4 + 1] = c1;
        sm[OFF_FT + tid * 4 + 2] = s2;
        sm[OFF_FT + tid * 4 + 3] = c2;
        sm[OFF_XD + tid * 2 + 0] = x.z;
        sm[OFF_XD + tid * 2 + 1] = x.w;
    } else {
        int t = tid - TILE;                       // 0..383
        const float4* W2v = (const float4*)W2;
        for (int i = t; i < HID * HID / 4; i += NT - TILE)
            *(float4*)&sm[OFF_W2 + i * 4] = W2v[i];
        for (int i = t; i < 4 * HID; i += NT - TILE) {
            int r = i >> 7, j = i & 127;          // W1 is [4][128]
            sm[OFF_W1T + j * 4 + r] = W1[i];
        }
        for (int i = t; i < HID; i += NT - TILE) {
            sm[OFF_B1 + i] = b1[i];
            sm[OFF_B2 + i] = b2[i];
            sm[OFF_W3 + i] = W3[i];
        }
    }
    __syncthreads();

    const int og8 = (tid >> 5) * 8;    // warp-uniform output group (k0 / j0)

    // ---------------- Phase A: h1row[s][j] = tanh(b1 + feat.W1T) ----------
    {
        const int s  = tid & 127;
        const int j0 = (tid >> 7) * 32;
        float4 f = *(const float4*)&sm[OFF_FT + s * 4];
        #pragma unroll
        for (int c = 0; c < 32; c += 4) {
            float hv[4];
            #pragma unroll
            for (int q = 0; q < 4; q++) {
                int j = j0 + c + q;
                float4 w = *(const float4*)&sm[OFF_W1T + j * 4];
                float z = sm[OFF_B1 + j] + f.x*w.x + f.y*w.y + f.z*w.z + f.w*w.w;
                hv[q] = tanh_hw(z);
            }
            *(float4*)&sm[OFF_H1 + s * RS + j0 + c]
                = make_float4(hv[0], hv[1], hv[2], hv[3]);
        }
    }
    __syncthreads();

    // ---------------- Phase B: z2 = h1@W2 (+b2); g2 = W3*sech^2 -----------
    // tile: 4 samples (lane+32u) x 8 k; j-loop in steps of 4
    {
        const int k0 = og8;
        ull acc[4][4];
        #pragma unroll
        for (int m = 0; m < 4; m++) {
            ull bp = pack2(sm[OFF_B2 + k0 + 2*m], sm[OFF_B2 + k0 + 2*m + 1]);
            acc[0][m] = bp; acc[1][m] = bp; acc[2][m] = bp; acc[3][m] = bp;
        }
        #pragma unroll 4
        for (int j = 0; j < HID; j += 4) {
            float hv[4][4];
            #pragma unroll
            for (int u = 0; u < 4; u++) {
                float4 h = *(const float4*)&sm[OFF_H1 + (lane + 32 * u) * RS + j];
                hv[u][0] = h.x; hv[u][1] = h.y; hv[u][2] = h.z; hv[u][3] = h.w;
            }
            #pragma unroll
            for (int q = 0; q < 4; q++) {
                F4U2 wlo, whi;
                wlo.f4 = *(const float4*)&sm[OFF_W2 + (j + q) * HID + k0];
                whi.f4 = *(const float4*)&sm[OFF_W2 + (j + q) * HID + k0 + 4];
                #pragma unroll
                for (int u = 0; u < 4; u++) {
                    ull hp = pack2(hv[u][q], hv[u][q]);
                    ffma2(acc[u][0], hp, wlo.u[0]);
                    ffma2(acc[u][1], hp, wlo.u[1]);
                    ffma2(acc[u][2], hp, whi.u[0]);
                    ffma2(acc[u][3], hp, whi.u[1]);
                }
            }
        }
        #pragma unroll
        for (int u = 0; u < 4; u++) {
            int s = lane + 32 * u;
            float g[8];
            #pragma unroll
            for (int m = 0; m < 4; m++) {
                float z0, z1;
                unpack2(acc[u][m], z0, z1);
                float t0 = tanh_hw(z0), t1 = tanh_hw(z1);
                g[2*m]     = sm[OFF_W3 + k0 + 2*m]     * (1.0f - t0 * t0);
                g[2*m + 1] = sm[OFF_W3 + k0 + 2*m + 1] * (1.0f - t1 * t1);
            }
            *(float4*)&sm[OFF_G2 + s * RS + k0]     = make_float4(g[0], g[1], g[2], g[3]);
            *(float4*)&sm[OFF_G2 + s * RS + k0 + 4] = make_float4(g[4], g[5], g[6], g[7]);
        }
    }
    __syncthreads();

    // ---------------- Phase C: a = g2@W2^T (k-dot); g1; gfeat partials ----
    float pf[4][4];
    {
        const int j0 = og8;
        ull acc[4][8];
        #pragma unroll
        for (int u = 0; u < 4; u++)
            #pragma unroll
            for (int jj = 0; jj < 8; jj++) acc[u][jj] = 0ull;

        #pragma unroll 2
        for (int k = 0; k < HID; k += 4) {
            F4U2 g[4];
            #pragma unroll
            for (int u = 0; u < 4; u++)
                g[u].f4 = *(const float4*)&sm[OFF_G2 + (lane + 32 * u) * RS + k];
            #pragma unroll
            for (int jj = 0; jj < 8; jj++) {
                F4U2 w; w.f4 = *(const float4*)&sm[OFF_W2 + (j0 + jj) * HID + k];
                #pragma unroll
                for (int u = 0; u < 4; u++) {
                    ffma2(acc[u][jj], g[u].u[0], w.u[0]);
                    ffma2(acc[u][jj], g[u].u[1], w.u[1]);
                }
            }
        }
        // epilogue (registers only): g1 = a*(1-h^2), gfeat partials
        #pragma unroll
        for (int u = 0; u < 4; u++) {
            int s = lane + 32 * u;
            float4 h0  = *(const float4*)&sm[OFF_H1 + s * RS + j0];
            float4 h1v = *(const float4*)&sm[OFF_H1 + s * RS + j0 + 4];
            float hh[8] = {h0.x, h0.y, h0.z, h0.w, h1v.x, h1v.y, h1v.z, h1v.w};
            float gf0 = 0.f, gf1 = 0.f, gf2 = 0.f, gf3 = 0.f;
            #pragma unroll
            for (int jj = 0; jj < 8; jj++) {
                float lo, hi;
                unpack2(acc[u][jj], lo, hi);
                float a = lo + hi;
                float g1v = a * (1.0f - hh[jj] * hh[jj]);
                float4 w = *(const float4*)&sm[OFF_W1T + (j0 + jj) * 4];
                gf0 = fmaf(g1v, w.x, gf0);
                gf1 = fmaf(g1v, w.y, gf1);
                gf2 = fmaf(g1v, w.z, gf2);
                gf3 = fmaf(g1v, w.w, gf3);
            }
            pf[u][0] = gf0; pf[u][1] = gf1; pf[u][2] = gf2; pf[u][3] = gf3;
        }
    }
    __syncthreads();   // all G2 reads done -> PF may overlay G2

    {
        const int jg = tid >> 5;   // 16 j-groups
        #pragma unroll
        for (int u = 0; u < 4; u++)
            *(float4*)&sm[OFF_PF + (jg * 128 + lane + 32 * u) * 4]
                = make_float4(pf[u][0], pf[u][1], pf[u][2], pf[u][3]);
    }
    __syncthreads();

    // ---------------- Reduce gfeat partials over the 16 j-groups ----------
    {
        int rs = tid >> 2, c = tid & 3;          // 512 threads: 128 s x 4 comps
        float a = 0.f;
        #pragma unroll
        for (int jg = 0; jg < 16; jg++)
            a += sm[OFF_PF + (jg * 128 + rs) * 4 + c];
        sm[OFF_GF + rs * 4 + c] = a;
    }
    __syncthreads();

    // ---------------- Final: analytic dynamics + output -------------------
    if (tid < TILE) {
        float4 gf = *(const float4*)&sm[OFF_GF + tid * 4];

        float w1 = sm[OFF_XD + tid * 2 + 0];
        float w2 = sm[OFF_XD + tid * 2 + 1];
        float s1 = sm[OFF_FT + tid * 4 + 0];
        float c1 = sm[OFF_FT + tid * 4 + 1];
        float s2 = sm[OFF_FT + tid * 4 + 2];
        float c2 = sm[OFF_FT + tid * 4 + 3];

        float sd = s1 * c2 - c1 * s2;      // sin(t1 - t2)
        float cd = c1 * c2 + s1 * s2;      // cos(t1 - t2)

        float dV1 = gf.x * c1 - gf.y * s1;
        float dV2 = gf.z * c2 - gf.w * s2;

        float tt  = w1 * w2 * sd;
        float dL1 = -tt - dV1;
        float dL2 =  tt - dV2;

        float cc = sd * (w2 - w1);
        float r1 = dL1 - w2 * cc;
        float r2 = dL2 - w1 * cc;

        float det  = 2.0f - cd * cd;
        float rdet = __fdividef(1.0f, det);
        float qdd1 = (r1 - cd * r2) * rdet;
        float qdd2 = (2.0f * r2 - cd * r1) * rdet;

        int gs = base + tid;
        if (gs < B)
            *(float4*)&out[gs * 4] = make_float4(w1, w2, qdd1, qdd2);
    }
}

extern "C" void kernel_launch(void* const* d_in, const int* in_sizes, int n_in,
                              void* d_out, int out_size)
{
    const float* X  = (const float*)d_in[0];
    const float* W1 = (const float*)d_in[1];
    const float* b1 = (const float*)d_in[2];
    const float* W2 = (const float*)d_in[3];
    const float* b2 = (const float*)d_in[4];
    const float* W3 = (const float*)d_in[5];
    // d_in[6] = b3: no effect on grad(V) -> unused
    float* out = (float*)d_out;

    int B = in_sizes[0] / 4;
    size_t smem = SMEM_FLOATS * sizeof(float);
    cudaFuncSetAttribute(lnn_kernel, cudaFuncAttributeMaxDynamicSharedMemorySize,
                         (int)smem);
    int grid = (B + TILE - 1) / TILE;
    lnn_kernel<<<grid, NT, smem>>>(X, W1, b1, W2, b2, W3, out, B);
}